// round 1
// baseline (speedup 1.0000x reference)
#include <cuda_runtime.h>
#include <cuda_bf16.h>
#include <cstdint>

// Problem constants (from reference):
//   B=16, H=90, LP=512, W=256, L=256 (W*L=65536), K=384
// cs:   (B, H, LP)  float32  -- only columns [0,384) are valid (rest NaN, never read)
// cs_p: (B, H, W*L) float32
// mask: (B, W*L)    int32, exactly K ones per batch
// out  = mean_{b,h,j} (cs[b,h,j] - cs_p[b,h,pos[b,j]])^2
// where pos[b] = increasing-order indices of mask[b]==1.

#define B_  16
#define H_  90
#define LP_ 512
#define WL_ 65536
#define K_  384

__device__ int g_pos[B_ * K_];

// ---------------------------------------------------------------------------
// Kernel 1: per-batch stable stream compaction of the mask.
// 16 blocks (one per batch), 1024 threads; each thread owns 64 contiguous
// mask elements (16 x int4 loads). Block-wide exclusive scan of per-thread
// one-counts gives the stable write offset.
// ---------------------------------------------------------------------------
__global__ void __launch_bounds__(1024) mask_compact_kernel(
    const int* __restrict__ mask, float* __restrict__ out)
{
    const int b = blockIdx.x;
    const int t = threadIdx.x;

    if (b == 0 && t == 0) out[0] = 0.0f;   // d_out is poisoned; zero it here

    const int4* m = reinterpret_cast<const int4*>(mask + (size_t)b * WL_) + (size_t)t * 16;

    int4 v[16];
    int cnt = 0;
#pragma unroll
    for (int i = 0; i < 16; i++) {
        v[i] = m[i];
        cnt += (v[i].x != 0) + (v[i].y != 0) + (v[i].z != 0) + (v[i].w != 0);
    }

    // Block exclusive scan of cnt (1024 threads = 32 warps)
    __shared__ int warpsums[32];
    const int lane = t & 31;
    const int wid  = t >> 5;

    int inc = cnt;  // warp-inclusive scan
#pragma unroll
    for (int o = 1; o < 32; o <<= 1) {
        int y = __shfl_up_sync(0xffffffffu, inc, o);
        if (lane >= o) inc += y;
    }
    if (lane == 31) warpsums[wid] = inc;
    __syncthreads();
    if (wid == 0) {
        int y = warpsums[lane];
#pragma unroll
        for (int o = 1; o < 32; o <<= 1) {
            int z = __shfl_up_sync(0xffffffffu, y, o);
            if (lane >= o) y += z;
        }
        warpsums[lane] = y;  // inclusive warp-sum scan
    }
    __syncthreads();

    int offset = (inc - cnt) + (wid > 0 ? warpsums[wid - 1] : 0);

    int* pos = g_pos + b * K_;
    const int base = t * 64;
#pragma unroll
    for (int i = 0; i < 16; i++) {
        int idx = base + i * 4;
        if (v[i].x != 0) pos[offset++] = idx + 0;
        if (v[i].y != 0) pos[offset++] = idx + 1;
        if (v[i].z != 0) pos[offset++] = idx + 2;
        if (v[i].w != 0) pos[offset++] = idx + 3;
    }
}

// ---------------------------------------------------------------------------
// Kernel 2: one block per (b, h) pair; thread j handles column j of K=384.
// Gathers cs_p at pos[b][j], squares the diff, block-reduces, atomically adds
// the pre-scaled partial to out[0].
// ---------------------------------------------------------------------------
__global__ void __launch_bounds__(K_) mse_kernel(
    const float* __restrict__ cs, const float* __restrict__ cs_p,
    float* __restrict__ out)
{
    const int bh = blockIdx.x;           // 0 .. B*H-1
    const int b  = bh / H_;
    const int j  = threadIdx.x;          // 0 .. 383

    const int p = g_pos[b * K_ + j];

    const float a = cs[(size_t)bh * LP_ + j];
    const float c = cs_p[(size_t)bh * WL_ + p];
    const float d = a - c;
    float s = d * d;

    // block reduce: 384 threads = 12 warps
    const int lane = j & 31;
    const int wid  = j >> 5;
#pragma unroll
    for (int o = 16; o > 0; o >>= 1)
        s += __shfl_down_sync(0xffffffffu, s, o);

    __shared__ float wsum[12];
    if (lane == 0) wsum[wid] = s;
    __syncthreads();

    if (wid == 0) {
        float v = (lane < 12) ? wsum[lane] : 0.0f;
#pragma unroll
        for (int o = 16; o > 0; o >>= 1)
            v += __shfl_down_sync(0xffffffffu, v, o);
        if (lane == 0) {
            const float scale = 1.0f / ((float)B_ * (float)H_ * (float)K_);
            atomicAdd(out, v * scale);
        }
    }
}

extern "C" void kernel_launch(void* const* d_in, const int* in_sizes, int n_in,
                              void* d_out, int out_size)
{
    const float* cs   = (const float*)d_in[0];  // (B, H, LP)
    const float* cs_p = (const float*)d_in[1];  // (B, H, W, L)
    const int*   mask = (const int*)d_in[2];    // (B, W, L)
    float* out = (float*)d_out;

    mask_compact_kernel<<<B_, 1024>>>(mask, out);
    mse_kernel<<<B_ * H_, K_>>>(cs, cs_p, out);
}

// round 3
// speedup vs baseline: 1.6054x; 1.6054x over previous
#include <cuda_runtime.h>
#include <cuda_bf16.h>
#include <cstdint>

// B=16, H=90, LP=512, W*L=65536, K=384
// out = mean_{b,h,j} (cs[b,h,j] - cs_p[b,h,pos[b,j]])^2
// pos[b] = ascending indices where mask[b]==1 (exactly K per batch).

#define B_   16
#define H_   90
#define LP_  512
#define WL_  65536
#define K_   384
#define HB_  3                  // heads per mse block
#define NW_  (WL_ / 32)         // 2048 bitmask words per batch

__device__ unsigned g_bits[B_ * NW_];
__device__ int g_pos[B_ * K_];

// ---------------------------------------------------------------------------
// Kernel A: pack int mask -> bitmask. 128 blocks (8 per batch) x 256 threads.
// Each thread packs 32 ints (8 x int4) into one u32 word. Full-chip read of 4MB.
// ---------------------------------------------------------------------------
__global__ void __launch_bounds__(256) mask_bits_kernel(
    const int* __restrict__ mask, float* __restrict__ out)
{
    if (blockIdx.x == 0 && threadIdx.x == 0) out[0] = 0.0f;  // d_out poisoned

    const int b     = blockIdx.x >> 3;        // 8 blocks per batch
    const int chunk = blockIdx.x & 7;
    const int t     = threadIdx.x;

    const int4* m = reinterpret_cast<const int4*>(
        mask + (size_t)b * WL_ + chunk * 8192 + t * 32);

    unsigned bits = 0;
#pragma unroll
    for (int i = 0; i < 8; i++) {
        int4 v = m[i];
        bits |= (unsigned)(v.x != 0) << (4 * i + 0);
        bits |= (unsigned)(v.y != 0) << (4 * i + 1);
        bits |= (unsigned)(v.z != 0) << (4 * i + 2);
        bits |= (unsigned)(v.w != 0) << (4 * i + 3);
    }
    g_bits[b * NW_ + chunk * 256 + t] = bits;
}

// ---------------------------------------------------------------------------
// Kernel B: stable compaction from bitmask. 16 blocks x 1024 threads.
// Each thread owns 2 words (64 indices); block-wide popcount scan gives the
// stable write offset. Reads only 8KB per block.
// ---------------------------------------------------------------------------
__global__ void __launch_bounds__(1024) mask_pos_kernel()
{
    const int b = blockIdx.x;
    const int t = threadIdx.x;

    const unsigned w0 = g_bits[b * NW_ + t * 2 + 0];
    const unsigned w1 = g_bits[b * NW_ + t * 2 + 1];
    int cnt = __popc(w0) + __popc(w1);

    // block exclusive scan (1024 threads = 32 warps)
    __shared__ int warpsums[32];
    const int lane = t & 31;
    const int wid  = t >> 5;

    int inc = cnt;
#pragma unroll
    for (int o = 1; o < 32; o <<= 1) {
        int y = __shfl_up_sync(0xffffffffu, inc, o);
        if (lane >= o) inc += y;
    }
    if (lane == 31) warpsums[wid] = inc;
    __syncthreads();
    if (wid == 0) {
        int y = warpsums[lane];
#pragma unroll
        for (int o = 1; o < 32; o <<= 1) {
            int z = __shfl_up_sync(0xffffffffu, y, o);
            if (lane >= o) y += z;
        }
        warpsums[lane] = y;
    }
    __syncthreads();

    int off = (inc - cnt) + (wid > 0 ? warpsums[wid - 1] : 0);
    int* pos = g_pos + b * K_;

    unsigned x = w0;
    int base = t * 64;
    while (x) { int i = __ffs(x) - 1; pos[off++] = base + i; x &= x - 1; }
    x = w1;
    base += 32;
    while (x) { int i = __ffs(x) - 1; pos[off++] = base + i; x &= x - 1; }
}

// ---------------------------------------------------------------------------
// Kernel C: MSE gather. One block handles HB_ heads of one batch; thread j
// owns column j for all HB_ heads (same gather index p -> pos load amortized,
// HB_ independent gathers in flight per thread).
// ---------------------------------------------------------------------------
__device__ __forceinline__ float ldg_evict_last(const float* p) {
    float v;
    asm("{\n\t"
        ".reg .b64 pol;\n\t"
        "createpolicy.fractional.L2::evict_last.b64 pol, 1.0;\n\t"
        "ld.global.nc.L2::cache_hint.f32 %0, [%1], pol;\n\t"
        "}"
        : "=f"(v) : "l"(p));
    return v;
}

__global__ void __launch_bounds__(K_) mse_kernel(
    const float* __restrict__ cs, const float* __restrict__ cs_p,
    float* __restrict__ out)
{
    const int blk = blockIdx.x;                  // 0 .. 16*(90/HB_)-1
    const int b   = blk / (H_ / HB_);
    const int h0  = (blk % (H_ / HB_)) * HB_;
    const int j   = threadIdx.x;

    const int p = g_pos[b * K_ + j];

    const float* csb  = cs   + ((size_t)(b * H_ + h0)) * LP_ + j;
    const float* cspb = cs_p + ((size_t)(b * H_ + h0)) * WL_ + p;

    float a[HB_], c[HB_];
#pragma unroll
    for (int r = 0; r < HB_; r++) c[r] = ldg_evict_last(cspb + (size_t)r * WL_);
#pragma unroll
    for (int r = 0; r < HB_; r++) a[r] = __ldg(csb + (size_t)r * LP_);

    float s = 0.0f;
#pragma unroll
    for (int r = 0; r < HB_; r++) { float d = a[r] - c[r]; s = fmaf(d, d, s); }

    // block reduce (384 threads = 12 warps)
    const int lane = j & 31;
    const int wid  = j >> 5;
#pragma unroll
    for (int o = 16; o > 0; o >>= 1)
        s += __shfl_down_sync(0xffffffffu, s, o);

    __shared__ float wsum[12];
    if (lane == 0) wsum[wid] = s;
    __syncthreads();

    if (wid == 0) {
        float v = (lane < 12) ? wsum[lane] : 0.0f;
#pragma unroll
        for (int o = 16; o > 0; o >>= 1)
            v += __shfl_down_sync(0xffffffffu, v, o);
        if (lane == 0) {
            const float scale = 1.0f / ((float)B_ * (float)H_ * (float)K_);
            atomicAdd(out, v * scale);
        }
    }
}

extern "C" void kernel_launch(void* const* d_in, const int* in_sizes, int n_in,
                              void* d_out, int out_size)
{
    const float* cs   = (const float*)d_in[0];  // (B, H, LP)
    const float* cs_p = (const float*)d_in[1];  // (B, H, W, L)
    const int*   mask = (const int*)d_in[2];    // (B, W, L)
    float* out = (float*)d_out;

    mask_bits_kernel<<<B_ * 8, 256>>>(mask, out);
    mask_pos_kernel<<<B_, 1024>>>();
    mse_kernel<<<B_ * (H_ / HB_), K_>>>(cs, cs_p, out);
}

// round 4
// speedup vs baseline: 1.6416x; 1.0226x over previous
#include <cuda_runtime.h>
#include <cuda_bf16.h>
#include <cstdint>

// B=16, H=90, LP=512, W*L=65536, K=384
// out = mean_{b,h,j} (cs[b,h,j] - cs_p[b,h,pos[b,j]])^2
// pos[b] = ascending indices where mask[b]==1 (exactly K per batch).

#define B_   16
#define H_   90
#define LP_  512
#define WL_  65536
#define K_   384
#define HB_  3                  // heads per mse block
#define NW_  (WL_ / 32)         // 2048 bitmask words per batch

__device__ unsigned g_bits[B_ * NW_];
__device__ int g_pos[B_ * K_];

// ---------------------------------------------------------------------------
// Kernel A: pack int mask -> bitmask, full-chip. 1024 blocks x 256 threads.
// Each thread loads ONE int4 (4 ints -> 4-bit nibble); a 3-step shfl_down
// tree packs 8 consecutive lanes' nibbles into one u32 word (every 8th lane
// stores). 262k threads saturate DRAM BW on the 4MB read.
// ---------------------------------------------------------------------------
__global__ void __launch_bounds__(256) mask_bits_kernel(
    const int* __restrict__ mask, float* __restrict__ out)
{
    if (blockIdx.x == 0 && threadIdx.x == 0) out[0] = 0.0f;  // d_out poisoned

    const int gt = blockIdx.x * 256 + threadIdx.x;           // 0 .. 262143
    const int4 v = reinterpret_cast<const int4*>(mask)[gt];

    unsigned x = (unsigned)(v.x != 0)
               | ((unsigned)(v.y != 0) << 1)
               | ((unsigned)(v.z != 0) << 2)
               | ((unsigned)(v.w != 0) << 3);

    // pack 8 lanes' nibbles -> 1 word (nibble of lane l+k lands at bits 4k..4k+3)
    x |= __shfl_down_sync(0xffffffffu, x, 1) << 4;
    x |= __shfl_down_sync(0xffffffffu, x, 2) << 8;
    x |= __shfl_down_sync(0xffffffffu, x, 4) << 16;

    if ((threadIdx.x & 7) == 0)
        g_bits[gt >> 3] = x;
}

// ---------------------------------------------------------------------------
// Kernel B: stable compaction from bitmask. 16 blocks x 1024 threads.
// Each thread owns 2 words (64 indices); block-wide popcount scan gives the
// stable write offset. Reads only 8KB per block.
// ---------------------------------------------------------------------------
__global__ void __launch_bounds__(1024) mask_pos_kernel()
{
    const int b = blockIdx.x;
    const int t = threadIdx.x;

    const unsigned w0 = g_bits[b * NW_ + t * 2 + 0];
    const unsigned w1 = g_bits[b * NW_ + t * 2 + 1];
    int cnt = __popc(w0) + __popc(w1);

    // block exclusive scan (1024 threads = 32 warps)
    __shared__ int warpsums[32];
    const int lane = t & 31;
    const int wid  = t >> 5;

    int inc = cnt;
#pragma unroll
    for (int o = 1; o < 32; o <<= 1) {
        int y = __shfl_up_sync(0xffffffffu, inc, o);
        if (lane >= o) inc += y;
    }
    if (lane == 31) warpsums[wid] = inc;
    __syncthreads();
    if (wid == 0) {
        int y = warpsums[lane];
#pragma unroll
        for (int o = 1; o < 32; o <<= 1) {
            int z = __shfl_up_sync(0xffffffffu, y, o);
            if (lane >= o) y += z;
        }
        warpsums[lane] = y;
    }
    __syncthreads();

    int off = (inc - cnt) + (wid > 0 ? warpsums[wid - 1] : 0);
    int* pos = g_pos + b * K_;

    unsigned x = w0;
    int base = t * 64;
    while (x) { int i = __ffs(x) - 1; pos[off++] = base + i; x &= x - 1; }
    x = w1;
    base += 32;
    while (x) { int i = __ffs(x) - 1; pos[off++] = base + i; x &= x - 1; }
}

// ---------------------------------------------------------------------------
// Kernel C: MSE gather. One block handles HB_ heads of one batch; thread j
// owns column j for all HB_ heads (same gather index p -> pos load amortized,
// HB_ independent gathers in flight per thread). evict_last keeps the 71MB
// of gathered lines resident in the 126MB L2 across graph replays.
// ---------------------------------------------------------------------------
__device__ __forceinline__ float ldg_evict_last(const float* p) {
    float v;
    asm("{\n\t"
        ".reg .b64 pol;\n\t"
        "createpolicy.fractional.L2::evict_last.b64 pol, 1.0;\n\t"
        "ld.global.nc.L2::cache_hint.f32 %0, [%1], pol;\n\t"
        "}"
        : "=f"(v) : "l"(p));
    return v;
}

__global__ void __launch_bounds__(K_) mse_kernel(
    const float* __restrict__ cs, const float* __restrict__ cs_p,
    float* __restrict__ out)
{
    const int blk = blockIdx.x;                  // 0 .. 16*(90/HB_)-1
    const int b   = blk / (H_ / HB_);
    const int h0  = (blk % (H_ / HB_)) * HB_;
    const int j   = threadIdx.x;

    const int p = g_pos[b * K_ + j];

    const float* csb  = cs   + ((size_t)(b * H_ + h0)) * LP_ + j;
    const float* cspb = cs_p + ((size_t)(b * H_ + h0)) * WL_ + p;

    float a[HB_], c[HB_];
#pragma unroll
    for (int r = 0; r < HB_; r++) c[r] = ldg_evict_last(cspb + (size_t)r * WL_);
#pragma unroll
    for (int r = 0; r < HB_; r++) a[r] = __ldg(csb + (size_t)r * LP_);

    float s = 0.0f;
#pragma unroll
    for (int r = 0; r < HB_; r++) { float d = a[r] - c[r]; s = fmaf(d, d, s); }

    // block reduce (384 threads = 12 warps)
    const int lane = j & 31;
    const int wid  = j >> 5;
#pragma unroll
    for (int o = 16; o > 0; o >>= 1)
        s += __shfl_down_sync(0xffffffffu, s, o);

    __shared__ float wsum[12];
    if (lane == 0) wsum[wid] = s;
    __syncthreads();

    if (wid == 0) {
        float v = (lane < 12) ? wsum[lane] : 0.0f;
#pragma unroll
        for (int o = 16; o > 0; o >>= 1)
            v += __shfl_down_sync(0xffffffffu, v, o);
        if (lane == 0) {
            const float scale = 1.0f / ((float)B_ * (float)H_ * (float)K_);
            atomicAdd(out, v * scale);
        }
    }
}

extern "C" void kernel_launch(void* const* d_in, const int* in_sizes, int n_in,
                              void* d_out, int out_size)
{
    const float* cs   = (const float*)d_in[0];  // (B, H, LP)
    const float* cs_p = (const float*)d_in[1];  // (B, H, W, L)
    const int*   mask = (const int*)d_in[2];    // (B, W, L)
    float* out = (float*)d_out;

    mask_bits_kernel<<<(B_ * WL_) / (4 * 256), 256>>>(mask, out);
    mask_pos_kernel<<<B_, 1024>>>();
    mse_kernel<<<B_ * (H_ / HB_), K_>>>(cs, cs_p, out);
}